// round 6
// baseline (speedup 1.0000x reference)
#include <cuda_runtime.h>
#include <cuda_bf16.h>

// PearsonLoss: x1 [8,32,256,256] f32, x2 same, margin [8,256,256] i32 -> scalar f32
//
// Streaming formulation over C=32 channels (no probability storage):
//   e1=exp(x1), e2=exp(x2); S1,S2,S11,S22,S12 running sums.
//   EX=EY=1/C exactly (softmax sums to 1).
//   score = (S12/(S1*S2*C) - 1/C^2) / sqrt((S11/(S1^2 C)-1/C^2)(S22/(S2^2 C)-1/C^2))
//   per_pixel = margin==0 ? 1-score : max(score,0);  out = mean.
//
// R6: WARP-COUNT fix. R2/R5 post-mortem: three structurally different kernels
// all ran 27.3us / DRAM 62.5% -> ptxas already batches loads; the binding
// constraint is 27.7 warps/SM (grid-offered) failing to hide 600-cyc DRAM
// latency interleaved with MUFU/FMA chains.
//  - Channels split across thread pairs: block=256, lower 128 threads do
//    ch 0-15 of 128 pixel-quads, upper 128 do ch 16-31 of the SAME quads.
//    Partials merged via smem [20][128] (conflict-free), lower half finalizes.
//  - 2x warps (8192 total, ~40 resident/SM at launch_bounds(256,5)),
//    same LDG.128 count, same coalescing, half the per-thread chain length.

#define C_CH   32
#define HW     65536          // 256*256
#define NBATCH 8
#define NPIX   (NBATCH * HW)  // 524288
#define NQUADS (NPIX / 4)     // 131072 pixel-quads
#define QUADS_PER_BLOCK 128
#define BLOCK_SIZE 256
#define NBLOCKS (NQUADS / QUADS_PER_BLOCK)   // 1024
#define CH_HALF 16

__device__ float        g_acc   = 0.0f;
__device__ unsigned int g_count = 0u;

__device__ __forceinline__ float finalize_pixel(float s1, float s2,
                                                float s11, float s22, float s12,
                                                int m) {
    const float invC  = 1.0f / 32.0f;
    const float invC2 = invC * invC;
    float r1 = __frcp_rn(s1);
    float r2 = __frcp_rn(s2);
    float vx  = fmaf(s11 * r1 * r1, invC, -invC2);   // EX2 - EX^2
    float vy  = fmaf(s22 * r2 * r2, invC, -invC2);   // EY2 - EY^2
    float num = fmaf(s12 * r1 * r2, invC, -invC2);   // EXY - EX*EY
    float score = num * rsqrtf(vx * vy);
    return (m == 0) ? (1.0f - score) : fmaxf(score, 0.0f);
}

__global__ void __launch_bounds__(BLOCK_SIZE, 5)
pearson_loss_kernel(const float* __restrict__ x1,
                    const float* __restrict__ x2,
                    const int*   __restrict__ margin,
                    float* __restrict__ out) {
    const int lt   = threadIdx.x & (QUADS_PER_BLOCK - 1);  // 0..127: quad lane
    const int half = threadIdx.x >> 7;                     // 0 or 1: channel half
    const int q    = blockIdx.x * QUADS_PER_BLOCK + lt;    // pixel-quad index
    const int p0   = q * 4;                                // base pixel
    const int b    = p0 >> 16;                             // / HW
    const int hw   = p0 & (HW - 1);

    // Base pointer for this thread's channel half.
    const float4* __restrict__ x1p =
        (const float4*)(x1 + (size_t)b * C_CH * HW + (size_t)half * CH_HALF * HW + hw);
    const float4* __restrict__ x2p =
        (const float4*)(x2 + (size_t)b * C_CH * HW + (size_t)half * CH_HALF * HW + hw);
    const int cstride4 = HW / 4;   // float4 stride per channel

    float4 S1  = make_float4(0.f, 0.f, 0.f, 0.f);
    float4 S2  = make_float4(0.f, 0.f, 0.f, 0.f);
    float4 S11 = make_float4(0.f, 0.f, 0.f, 0.f);
    float4 S22 = make_float4(0.f, 0.f, 0.f, 0.f);
    float4 S12 = make_float4(0.f, 0.f, 0.f, 0.f);

#pragma unroll
    for (int c = 0; c < CH_HALF; c++) {
        float4 a = __ldcs(&x1p[c * cstride4]);
        float4 v = __ldcs(&x2p[c * cstride4]);

        float e1, e2;
        e1 = __expf(a.x); e2 = __expf(v.x);
        S1.x += e1; S2.x += e2;
        S11.x = fmaf(e1, e1, S11.x); S22.x = fmaf(e2, e2, S22.x);
        S12.x = fmaf(e1, e2, S12.x);

        e1 = __expf(a.y); e2 = __expf(v.y);
        S1.y += e1; S2.y += e2;
        S11.y = fmaf(e1, e1, S11.y); S22.y = fmaf(e2, e2, S22.y);
        S12.y = fmaf(e1, e2, S12.y);

        e1 = __expf(a.z); e2 = __expf(v.z);
        S1.z += e1; S2.z += e2;
        S11.z = fmaf(e1, e1, S11.z); S22.z = fmaf(e2, e2, S22.z);
        S12.z = fmaf(e1, e2, S12.z);

        e1 = __expf(a.w); e2 = __expf(v.w);
        S1.w += e1; S2.w += e2;
        S11.w = fmaf(e1, e1, S11.w); S22.w = fmaf(e2, e2, S22.w);
        S12.w = fmaf(e1, e2, S12.w);
    }

    // Merge the two channel-halves through smem. Layout [20][128]:
    // consecutive lt -> consecutive addresses, conflict-free for both halves.
    __shared__ float smem_p[20][QUADS_PER_BLOCK];
    if (half == 1) {
        smem_p[ 0][lt] = S1.x;  smem_p[ 1][lt] = S1.y;
        smem_p[ 2][lt] = S1.z;  smem_p[ 3][lt] = S1.w;
        smem_p[ 4][lt] = S2.x;  smem_p[ 5][lt] = S2.y;
        smem_p[ 6][lt] = S2.z;  smem_p[ 7][lt] = S2.w;
        smem_p[ 8][lt] = S11.x; smem_p[ 9][lt] = S11.y;
        smem_p[10][lt] = S11.z; smem_p[11][lt] = S11.w;
        smem_p[12][lt] = S22.x; smem_p[13][lt] = S22.y;
        smem_p[14][lt] = S22.z; smem_p[15][lt] = S22.w;
        smem_p[16][lt] = S12.x; smem_p[17][lt] = S12.y;
        smem_p[18][lt] = S12.z; smem_p[19][lt] = S12.w;
    }
    __syncthreads();

    float local = 0.0f;
    if (half == 0) {
        S1.x  += smem_p[ 0][lt]; S1.y  += smem_p[ 1][lt];
        S1.z  += smem_p[ 2][lt]; S1.w  += smem_p[ 3][lt];
        S2.x  += smem_p[ 4][lt]; S2.y  += smem_p[ 5][lt];
        S2.z  += smem_p[ 6][lt]; S2.w  += smem_p[ 7][lt];
        S11.x += smem_p[ 8][lt]; S11.y += smem_p[ 9][lt];
        S11.z += smem_p[10][lt]; S11.w += smem_p[11][lt];
        S22.x += smem_p[12][lt]; S22.y += smem_p[13][lt];
        S22.z += smem_p[14][lt]; S22.w += smem_p[15][lt];
        S12.x += smem_p[16][lt]; S12.y += smem_p[17][lt];
        S12.z += smem_p[18][lt]; S12.w += smem_p[19][lt];

        const int4 mg = __ldg(&((const int4*)margin)[q]);
        local = finalize_pixel(S1.x, S2.x, S11.x, S22.x, S12.x, mg.x)
              + finalize_pixel(S1.y, S2.y, S11.y, S22.y, S12.y, mg.y)
              + finalize_pixel(S1.z, S2.z, S11.z, S22.z, S12.z, mg.z)
              + finalize_pixel(S1.w, S2.w, S11.w, S22.w, S12.w, mg.w);
    }

    // Block reduce (upper half contributes 0).
#pragma unroll
    for (int off = 16; off > 0; off >>= 1)
        local += __shfl_xor_sync(0xFFFFFFFF, local, off);

    __shared__ float warp_sums[BLOCK_SIZE / 32];
    const int lane = threadIdx.x & 31;
    const int wid  = threadIdx.x >> 5;
    if (lane == 0) warp_sums[wid] = local;
    __syncthreads();

    __shared__ bool is_last;
    if (threadIdx.x == 0) {
        float s = warp_sums[0];
#pragma unroll
        for (int w = 1; w < BLOCK_SIZE / 32; w++) s += warp_sums[w];
        atomicAdd(&g_acc, s);
        __threadfence();
        unsigned prev = atomicAdd(&g_count, 1u);
        is_last = (prev == (unsigned)(NBLOCKS - 1));
    }
    __syncthreads();

    if (is_last && threadIdx.x == 0) {
        __threadfence();  // make all g_acc contributions visible
        float total = *((volatile float*)&g_acc);
        out[0] = total * (1.0f / (float)NPIX);
        // reset for next graph replay (deterministic relaunch)
        g_acc   = 0.0f;
        g_count = 0u;
    }
}

extern "C" void kernel_launch(void* const* d_in, const int* in_sizes, int n_in,
                              void* d_out, int out_size) {
    const float* x1     = (const float*)d_in[0];
    const float* x2     = (const float*)d_in[1];
    const int*   margin = (const int*)d_in[2];
    float* out = (float*)d_out;

    pearson_loss_kernel<<<NBLOCKS, BLOCK_SIZE>>>(x1, x2, margin, out);
}